// round 1
// baseline (speedup 1.0000x reference)
#include <cuda_runtime.h>
#include <cuda_bf16.h>
#include <math.h>

// Shapes (fixed for this problem)
// B=2, L=2048, DM=1024, DI=2048, N=16, DC=4, DT=64
#define BB 2
#define LL 2048
#define DM 1024
#define DI 2048
#define NS 16
#define DC 4
#define DT 64
#define ROWS (BB*LL)          // 4096
#define XZW (2*DI)            // 4096
#define DBLW (DT + 2*NS)      // 96

// ---------------- scratch (device globals; no runtime allocation) -------------
__device__ float g_xn[ROWS * DM];        // 16 MB
__device__ float g_xz[ROWS * XZW];       // 64 MB  (xi | z)
__device__ float g_u [ROWS * DI];        // 32 MB
__device__ float g_dbl[ROWS * DBLW];     // 1.5 MB (dt | B | C)
__device__ float g_delta[ROWS * DI];     // 32 MB
__device__ float g_y [ROWS * DI];        // 32 MB

// ---------------- helpers ----------------
__device__ __forceinline__ float siluf(float a) {
    return a / (1.0f + expf(-a));
}
__device__ __forceinline__ float softplusf(float a) {
    // stable softplus
    if (a > 20.0f) return a;
    return log1pf(expf(a));
}

// ---------------- LayerNorm ----------------
// one block per row, 256 threads, DM=1024 -> 4 floats/thread (float4)
__global__ void ln_kernel(const float* __restrict__ x,
                          const float* __restrict__ gam,
                          const float* __restrict__ bet,
                          float* __restrict__ xn) {
    int row = blockIdx.x;
    const float4* xr = reinterpret_cast<const float4*>(x + (size_t)row * DM);
    int t = threadIdx.x;
    float4 v = xr[t];
    float s  = v.x + v.y + v.z + v.w;
    float ss = v.x*v.x + v.y*v.y + v.z*v.z + v.w*v.w;
    // warp reduce
    #pragma unroll
    for (int o = 16; o > 0; o >>= 1) {
        s  += __shfl_xor_sync(0xffffffff, s,  o);
        ss += __shfl_xor_sync(0xffffffff, ss, o);
    }
    __shared__ float rs[8], rss[8];
    int wid = t >> 5, lid = t & 31;
    if (lid == 0) { rs[wid] = s; rss[wid] = ss; }
    __syncthreads();
    __shared__ float smu, srstd;
    if (t == 0) {
        float ts = 0.f, tss = 0.f;
        #pragma unroll
        for (int i = 0; i < 8; i++) { ts += rs[i]; tss += rss[i]; }
        float mu = ts / (float)DM;
        float var = tss / (float)DM - mu * mu;
        smu = mu;
        srstd = rsqrtf(var + 1e-5f);
    }
    __syncthreads();
    float mu = smu, rstd = srstd;
    const float4* g4 = reinterpret_cast<const float4*>(gam);
    const float4* b4 = reinterpret_cast<const float4*>(bet);
    float4 gg = g4[t], bb = b4[t];
    float4 o;
    o.x = (v.x - mu) * rstd * gg.x + bb.x;
    o.y = (v.y - mu) * rstd * gg.y + bb.y;
    o.z = (v.z - mu) * rstd * gg.z + bb.z;
    o.w = (v.w - mu) * rstd * gg.w + bb.w;
    reinterpret_cast<float4*>(xn + (size_t)row * DM)[t] = o;
}

// ---------------- Generic tiled fp32 GEMM ----------------
// C[M,N] = A[M,K (row stride lda)] * B[K,N] (+ epilogue)
// EPI: 0 = none, 1 = C += E (residual, stride N), 2 = softplus(C + E[col]) (bias)
// BM=BN=128, BK=16, 256 threads, 8x8 per thread.
// Requires: M % 128 == 0, K % 16 == 0. N arbitrary (guarded).
template<int EPI>
__global__ void gemm128(const float* __restrict__ A,
                        const float* __restrict__ B,
                        const float* __restrict__ E,
                        float* __restrict__ C,
                        int M, int N, int K, int lda) {
    __shared__ float As[16][128];
    __shared__ float Bs[16][128];
    int m0 = blockIdx.y * 128;
    int n0 = blockIdx.x * 128;
    int t = threadIdx.x;            // 0..255
    int ty = t >> 4;                // 0..15 (m group)
    int tx = t & 15;                // 0..15 (n group)

    float acc[8][8];
    #pragma unroll
    for (int i = 0; i < 8; i++)
        #pragma unroll
        for (int j = 0; j < 8; j++) acc[i][j] = 0.f;

    for (int kt = 0; kt < K; kt += 16) {
        // load A tile: 128 x 16, transposed into As[k][m]
        #pragma unroll
        for (int i = 0; i < 8; i++) {
            int idx = t + i * 256;           // 0..2047
            int m = idx >> 4, k = idx & 15;
            As[k][m] = A[(size_t)(m0 + m) * lda + kt + k];
        }
        // load B tile: 16 x 128 into Bs[k][n]
        #pragma unroll
        for (int i = 0; i < 8; i++) {
            int idx = t + i * 256;
            int k = idx >> 7, n = idx & 127;
            int col = n0 + n;
            Bs[k][n] = (col < N) ? B[(size_t)(kt + k) * N + col] : 0.f;
        }
        __syncthreads();
        #pragma unroll
        for (int k = 0; k < 16; k++) {
            float a[8], b[8];
            #pragma unroll
            for (int j = 0; j < 8; j++) a[j] = As[k][ty * 8 + j];
            #pragma unroll
            for (int j = 0; j < 8; j++) b[j] = Bs[k][tx * 8 + j];
            #pragma unroll
            for (int i = 0; i < 8; i++)
                #pragma unroll
                for (int j = 0; j < 8; j++)
                    acc[i][j] = fmaf(a[i], b[j], acc[i][j]);
        }
        __syncthreads();
    }

    #pragma unroll
    for (int i = 0; i < 8; i++) {
        int row = m0 + ty * 8 + i;
        #pragma unroll
        for (int j = 0; j < 8; j++) {
            int col = n0 + tx * 8 + j;
            if (col < N) {
                float v = acc[i][j];
                if (EPI == 1) v += E[(size_t)row * N + col];
                if (EPI == 2) v = softplusf(v + E[col]);
                C[(size_t)row * N + col] = v;
            }
        }
    }
}

// ---------------- Depthwise causal conv (DC=4) + SiLU ----------------
// u[b,l,d] = silu( sum_{j=0..3} xi[b, l-3+j, d] * cw[d,j] + cb[d] )
// xi = g_xz[row*4096 + d]
__global__ void conv_silu_kernel(const float* __restrict__ xz,
                                 const float* __restrict__ cw,
                                 const float* __restrict__ cb,
                                 float* __restrict__ u) {
    int idx = blockIdx.x * blockDim.x + threadIdx.x;
    if (idx >= ROWS * DI) return;
    int d = idx & (DI - 1);
    int row = idx >> 11;            // / DI
    int b = row >> 11;              // / LL
    int l = row & (LL - 1);
    float w0 = cw[d * DC + 0], w1 = cw[d * DC + 1], w2 = cw[d * DC + 2], w3 = cw[d * DC + 3];
    float acc = cb[d];
    int base = (b * LL) * XZW + d;
    if (l >= 3) acc = fmaf(xz[base + (size_t)(l - 3) * XZW], w0, acc);
    if (l >= 2) acc = fmaf(xz[base + (size_t)(l - 2) * XZW], w1, acc);
    if (l >= 1) acc = fmaf(xz[base + (size_t)(l - 1) * XZW], w2, acc);
    acc = fmaf(xz[base + (size_t)l * XZW], w3, acc);
    u[idx] = siluf(acc);
}

// ---------------- Selective scan ----------------
// grid = BB * (DI/128) = 32 blocks, 128 threads; each thread owns one channel d.
// For each l: dA[n]=exp(delta*A[n]); h[n]=dA*h + delta*u*Bm[n]; y=sum h*Cm
// output: y_out = (y + u*Dskip) * silu(z)
__global__ void scan_kernel(const float* __restrict__ dbl,
                            const float* __restrict__ delta,
                            const float* __restrict__ u,
                            const float* __restrict__ xz,
                            const float* __restrict__ A_log,
                            const float* __restrict__ Dskip,
                            float* __restrict__ y) {
    int b = blockIdx.x >> 4;                 // / 16
    int dgrp = blockIdx.x & 15;
    int d = dgrp * 128 + threadIdx.x;

    float A[NS];
    #pragma unroll
    for (int n = 0; n < NS; n++) A[n] = -expf(A_log[d * NS + n]);
    float h[NS];
    #pragma unroll
    for (int n = 0; n < NS; n++) h[n] = 0.f;
    float Dd = Dskip[d];

    __shared__ float Bs[NS], Cs[NS];

    for (int l = 0; l < LL; l++) {
        int row = b * LL + l;
        if (threadIdx.x < NS) Bs[threadIdx.x] = dbl[(size_t)row * DBLW + DT + threadIdx.x];
        else if (threadIdx.x < 2 * NS) Cs[threadIdx.x - NS] = dbl[(size_t)row * DBLW + DT + NS + (threadIdx.x - NS)];
        __syncthreads();
        float dl = delta[(size_t)row * DI + d];
        float ul = u[(size_t)row * DI + d];
        float su = dl * ul;
        float acc = 0.f;
        #pragma unroll
        for (int n = 0; n < NS; n++) {
            float dA = __expf(dl * A[n]);
            h[n] = fmaf(dA, h[n], su * Bs[n]);
            acc = fmaf(h[n], Cs[n], acc);
        }
        float z = xz[(size_t)row * XZW + DI + d];
        float sz = z / (1.0f + expf(-z));
        y[(size_t)row * DI + d] = (acc + ul * Dd) * sz;
        __syncthreads();
    }
}

// ---------------- launch ----------------
extern "C" void kernel_launch(void* const* d_in, const int* in_sizes, int n_in,
                              void* d_out, int out_size) {
    const float* x      = (const float*)d_in[0];
    const float* ln_g   = (const float*)d_in[1];
    const float* ln_b   = (const float*)d_in[2];
    const float* W_in   = (const float*)d_in[3];
    const float* conv_w = (const float*)d_in[4];
    const float* conv_b = (const float*)d_in[5];
    const float* W_x    = (const float*)d_in[6];
    const float* W_dt   = (const float*)d_in[7];
    const float* b_dt   = (const float*)d_in[8];
    const float* A_log  = (const float*)d_in[9];
    const float* Dskip  = (const float*)d_in[10];
    const float* W_out  = (const float*)d_in[11];
    float* out = (float*)d_out;

    float *xn, *xz, *u, *dbl, *delta, *y;
    cudaGetSymbolAddress((void**)&xn,    g_xn);
    cudaGetSymbolAddress((void**)&xz,    g_xz);
    cudaGetSymbolAddress((void**)&u,     g_u);
    cudaGetSymbolAddress((void**)&dbl,   g_dbl);
    cudaGetSymbolAddress((void**)&delta, g_delta);
    cudaGetSymbolAddress((void**)&y,     g_y);

    // 1. LayerNorm
    ln_kernel<<<ROWS, 256>>>(x, ln_g, ln_b, xn);

    // 2. xz = xn @ W_in   [4096,1024]x[1024,4096]
    gemm128<0><<<dim3(XZW / 128, ROWS / 128), 256>>>(xn, W_in, nullptr, xz,
                                                     ROWS, XZW, DM, DM);

    // 3. depthwise conv + silu -> u
    {
        int total = ROWS * DI;
        conv_silu_kernel<<<(total + 255) / 256, 256>>>(xz, conv_w, conv_b, u);
    }

    // 4. dbl = u @ W_x   [4096,2048]x[2048,96]
    gemm128<0><<<dim3(1, ROWS / 128), 256>>>(u, W_x, nullptr, dbl,
                                             ROWS, DBLW, DI, DI);

    // 5. delta = softplus(dt @ W_dt + b_dt)   [4096,64]x[64,2048]
    gemm128<2><<<dim3(DI / 128, ROWS / 128), 256>>>(dbl, W_dt, b_dt, delta,
                                                    ROWS, DI, DT, DBLW);

    // 6. selective scan + skip + gate -> y
    scan_kernel<<<BB * (DI / 128), 128>>>(dbl, delta, u, xz, A_log, Dskip, y);

    // 7. out = x + y @ W_out   [4096,2048]x[2048,1024]
    gemm128<1><<<dim3(DM / 128, ROWS / 128), 256>>>(y, W_out, x, out,
                                                    ROWS, DM, DI, DI);
}

// round 3
// speedup vs baseline: 2.1273x; 2.1273x over previous
#include <cuda_runtime.h>
#include <cuda_bf16.h>
#include <cstdint>
#include <math.h>

// Shapes (fixed): B=2, L=2048, DM=1024, DI=2048, N=16, DC=4, DT=64
#define BB 2
#define LL 2048
#define DM 1024
#define DI 2048
#define NS 16
#define DC 4
#define DT 64
#define ROWS (BB*LL)          // 4096
#define XZW (2*DI)            // 4096
#define DBLW 128              // padded dbl row (dt 0..63 | B 64..79 | C 80..95 | pad)

// ================= scratch (device globals) =================
__device__ __align__(256) float g_xz[ROWS * XZW];                  // xi | z (fp32)
__device__ __align__(256) float g_u [ROWS * DI];
__device__ __align__(256) float g_dblp[4 * ROWS * DBLW];           // split-K partials
__device__ __align__(256) float g_dblr[ROWS * DBLW];               // reduced
__device__ __align__(256) float g_delta[ROWS * DI];
__device__ __align__(256) __nv_bfloat16 g_xn_h[ROWS * DM],  g_xn_l[ROWS * DM];
__device__ __align__(256) __nv_bfloat16 g_u_h [ROWS * DI],  g_u_l [ROWS * DI];
__device__ __align__(256) __nv_bfloat16 g_dt_h[ROWS * DT],  g_dt_l[ROWS * DT];
__device__ __align__(256) __nv_bfloat16 g_y_h [ROWS * DI],  g_y_l [ROWS * DI];
__device__ __align__(256) __nv_bfloat16 g_win_h[XZW * DM],  g_win_l[XZW * DM];   // [4096,1024]
__device__ __align__(256) __nv_bfloat16 g_wx_h [128 * DI],  g_wx_l [128 * DI];   // [128,2048]
__device__ __align__(256) __nv_bfloat16 g_wdt_h[DI * DT],   g_wdt_l[DI * DT];    // [2048,64]
__device__ __align__(256) __nv_bfloat16 g_wout_h[DM * DI],  g_wout_l[DM * DI];   // [1024,2048]

__device__ __forceinline__ void split_bf16(float v, __nv_bfloat16& h, __nv_bfloat16& l) {
    h = __float2bfloat16(v);
    l = __float2bfloat16(v - __bfloat162float(h));
}

// ================= PTX helpers (baseline compute_103 ISA only) =================
__device__ __forceinline__ uint32_t smem_u32(const void* p) {
    uint32_t a;
    asm("{ .reg .u64 t; cvta.to.shared.u64 t, %1; cvt.u32.u64 %0, t; }" : "=r"(a) : "l"(p));
    return a;
}
__device__ __forceinline__ void cp_async16(uint32_t sa, const void* ga) {
    asm volatile("cp.async.cg.shared.global [%0], [%1], 16;" :: "r"(sa), "l"(ga));
}
__device__ __forceinline__ void cp_commit() {
    asm volatile("cp.async.commit_group;" ::: "memory");
}
__device__ __forceinline__ void cp_wait1() {
    asm volatile("cp.async.wait_group 1;" ::: "memory");
}
__device__ __forceinline__ void cp_wait0() {
    asm volatile("cp.async.wait_group 0;" ::: "memory");
}
__device__ __forceinline__ void ldsm4(uint32_t* r, uint32_t addr) {
    asm volatile("ldmatrix.sync.aligned.m8n8.x4.shared.b16 {%0,%1,%2,%3}, [%4];"
        : "=r"(r[0]), "=r"(r[1]), "=r"(r[2]), "=r"(r[3]) : "r"(addr));
}
__device__ __forceinline__ void mma16816(float* d, const uint32_t* a, const uint32_t* b) {
    asm volatile("mma.sync.aligned.m16n8k16.row.col.f32.bf16.bf16.f32 "
        "{%0,%1,%2,%3}, {%4,%5,%6,%7}, {%8,%9}, {%0,%1,%2,%3};"
        : "+f"(d[0]), "+f"(d[1]), "+f"(d[2]), "+f"(d[3])
        : "r"(a[0]), "r"(a[1]), "r"(a[2]), "r"(a[3]), "r"(b[0]), "r"(b[1]));
}
// swizzled smem byte offset for (row, 16B-chunk) in a [128 rows x 64B] tile
__device__ __forceinline__ uint32_t sw_off(int row, int chunk) {
    return (uint32_t)(row * 64 + ((chunk ^ ((row >> 1) & 3)) << 4));
}

// ================= LayerNorm -> bf16 hi/lo =================
__global__ void ln_kernel(const float* __restrict__ x,
                          const float* __restrict__ gam,
                          const float* __restrict__ bet,
                          __nv_bfloat16* __restrict__ xnh,
                          __nv_bfloat16* __restrict__ xnl) {
    int row = blockIdx.x;
    const float4* xr = reinterpret_cast<const float4*>(x + (size_t)row * DM);
    int t = threadIdx.x;
    float4 v = xr[t];
    float s  = v.x + v.y + v.z + v.w;
    float ss = v.x*v.x + v.y*v.y + v.z*v.z + v.w*v.w;
    #pragma unroll
    for (int o = 16; o > 0; o >>= 1) {
        s  += __shfl_xor_sync(0xffffffff, s,  o);
        ss += __shfl_xor_sync(0xffffffff, ss, o);
    }
    __shared__ float rs[8], rss[8];
    int wid = t >> 5, lid = t & 31;
    if (lid == 0) { rs[wid] = s; rss[wid] = ss; }
    __syncthreads();
    __shared__ float smu, srstd;
    if (t == 0) {
        float ts = 0.f, tss = 0.f;
        #pragma unroll
        for (int i = 0; i < 8; i++) { ts += rs[i]; tss += rss[i]; }
        float mu = ts / (float)DM;
        float var = tss / (float)DM - mu * mu;
        smu = mu; srstd = rsqrtf(var + 1e-5f);
    }
    __syncthreads();
    float mu = smu, rstd = srstd;
    const float4* g4 = reinterpret_cast<const float4*>(gam);
    const float4* b4 = reinterpret_cast<const float4*>(bet);
    float4 gg = g4[t], bb = b4[t];
    float o0 = (v.x - mu) * rstd * gg.x + bb.x;
    float o1 = (v.y - mu) * rstd * gg.y + bb.y;
    float o2 = (v.z - mu) * rstd * gg.z + bb.z;
    float o3 = (v.w - mu) * rstd * gg.w + bb.w;
    __nv_bfloat16 h0,l0,h1,l1,h2,l2,h3,l3;
    split_bf16(o0,h0,l0); split_bf16(o1,h1,l1); split_bf16(o2,h2,l2); split_bf16(o3,h3,l3);
    __nv_bfloat162* ph = reinterpret_cast<__nv_bfloat162*>(xnh + (size_t)row * DM);
    __nv_bfloat162* pl = reinterpret_cast<__nv_bfloat162*>(xnl + (size_t)row * DM);
    ph[t*2]   = __halves2bfloat162(h0, h1);
    ph[t*2+1] = __halves2bfloat162(h2, h3);
    pl[t*2]   = __halves2bfloat162(l0, l1);
    pl[t*2+1] = __halves2bfloat162(l2, l3);
}

// ============ weight transpose + bf16 split:  W[K,N] -> T[Npad,K] ============
__global__ void wtrans_kernel(const float* __restrict__ W,
                              __nv_bfloat16* __restrict__ Th,
                              __nv_bfloat16* __restrict__ Tl,
                              int K, int N, int Npad) {
    __shared__ float t[32][33];
    int n = blockIdx.x * 32 + threadIdx.x;
    int k0 = blockIdx.y * 32;
    #pragma unroll
    for (int i = 0; i < 4; i++) {
        int k = k0 + threadIdx.y + i * 8;
        t[threadIdx.y + i * 8][threadIdx.x] = (n < N) ? W[(size_t)k * N + n] : 0.f;
    }
    __syncthreads();
    int kw = k0 + threadIdx.x;
    #pragma unroll
    for (int i = 0; i < 4; i++) {
        int nn = blockIdx.x * 32 + threadIdx.y + i * 8;
        if (nn < Npad) {
            float v = t[threadIdx.x][threadIdx.y + i * 8];
            __nv_bfloat16 h, l;
            split_bf16(v, h, l);
            Th[(size_t)nn * K + kw] = h;
            Tl[(size_t)nn * K + kw] = l;
        }
    }
}

// ================= mma.sync GEMM =================
// C[4096, N<=128*gx] = (Ah+Al)[4096,K] @ (Bh+Bl)^T, B stored [Npad,K] bf16 K-major.
// 3 segments (AhBh, AhBl, AlBh). CTA tile 128x128, BK=32, 8 warps (64x32 each).
// Split-K via gridDim.z: each z handles nkt k-tiles starting at z*nkt, writes
// C + z*zstride.  EPI: 0 none, 1 +E[row*ldc+col], 2 softplus(v + E[col]).
template<int EPI>
__global__ void __launch_bounds__(256, 2) mma_gemm(
    const __nv_bfloat16* __restrict__ Ah, const __nv_bfloat16* __restrict__ Al,
    const __nv_bfloat16* __restrict__ Bh, const __nv_bfloat16* __restrict__ Bl,
    const float* __restrict__ E, float* __restrict__ C,
    int N, int lda, int ldc, int nkt, size_t zstride) {
    __shared__ __align__(128) char sm[2][16384];   // per stage: A 8KB | B 8KB
    const int tid = threadIdx.x, lane = tid & 31, wid = tid >> 5;
    const int m0 = blockIdx.y * 128, n0 = blockIdx.x * 128;
    const int wm = (wid >> 2) * 64, wn = (wid & 3) * 32;
    const int kt0 = blockIdx.z * nkt;
    C += (size_t)blockIdx.z * zstride;

    const uint32_t sb = smem_u32(sm);
    const int T = 3 * nkt;

    float d[4][4][4];
    #pragma unroll
    for (int a = 0; a < 4; a++)
        #pragma unroll
        for (int b = 0; b < 4; b++)
            #pragma unroll
            for (int c = 0; c < 4; c++) d[a][b][c] = 0.f;

    auto load_tile = [&](int i, int buf) {
        int seg = i / nkt;
        int kt = kt0 + (i - seg * nkt);
        const __nv_bfloat16* As = (seg == 2) ? Al : Ah;
        const __nv_bfloat16* Bs = (seg == 1) ? Bl : Bh;
        uint32_t dst = sb + buf * 16384;
        #pragma unroll
        for (int j = 0; j < 4; j++) {
            int chunk = tid + j * 256;           // 0..1023
            int isB = chunk >> 9;
            int c5 = chunk & 511;
            int row = c5 >> 2, c = c5 & 3;
            const __nv_bfloat16* src = isB ? Bs : As;
            int g0 = (isB ? n0 : m0) + row;
            const void* gp = (const char*)(src + (size_t)g0 * lda + kt * 32) + c * 16;
            cp_async16(dst + (isB << 13) + sw_off(row, c), gp);
        }
        cp_commit();
    };

    load_tile(0, 0);
    for (int i = 0; i < T; i++) {
        int buf = i & 1;
        if (i + 1 < T) { load_tile(i + 1, buf ^ 1); cp_wait1(); }
        else cp_wait0();
        __syncthreads();

        uint32_t abase = sb + buf * 16384;
        uint32_t bbase = abase + 8192;
        int lrow = lane & 15, lk = lane >> 4;
        #pragma unroll
        for (int ks = 0; ks < 2; ks++) {
            uint32_t a[4][4], bf[4][2];
            #pragma unroll
            for (int mi = 0; mi < 4; mi++)
                ldsm4(a[mi], abase + sw_off(wm + mi * 16 + lrow, ks * 2 + lk));
            #pragma unroll
            for (int nj = 0; nj < 2; nj++) {
                uint32_t t4[4];
                ldsm4(t4, bbase + sw_off(wn + nj * 16 + lrow, ks * 2 + lk));
                bf[nj*2][0] = t4[0]; bf[nj*2][1] = t4[2];
                bf[nj*2+1][0] = t4[1]; bf[nj*2+1][1] = t4[3];
            }
            #pragma unroll
            for (int mi = 0; mi < 4; mi++)
                #pragma unroll
                for (int ni = 0; ni < 4; ni++)
                    mma16816(d[mi][ni], a[mi], bf[ni]);
        }
        __syncthreads();
    }

    // epilogue: direct register -> gmem
    #pragma unroll
    for (int mi = 0; mi < 4; mi++) {
        #pragma unroll
        for (int ni = 0; ni < 4; ni++) {
            int r = m0 + wm + mi * 16 + (lane >> 2);
            int col = n0 + wn + ni * 8 + (lane & 3) * 2;
            if (col < N) {
                #pragma unroll
                for (int h = 0; h < 2; h++) {
                    int rr = r + h * 8;
                    float v0 = d[mi][ni][h*2], v1 = d[mi][ni][h*2+1];
                    size_t off = (size_t)rr * ldc + col;
                    if (EPI == 1) {
                        v0 += E[off]; v1 += E[off + 1];
                    } else if (EPI == 2) {
                        float a0 = v0 + E[col], a1 = v1 + E[col + 1];
                        v0 = (a0 > 20.f) ? a0 : log1pf(__expf(a0));
                        v1 = (a1 > 20.f) ? a1 : log1pf(__expf(a1));
                    }
                    *reinterpret_cast<float2*>(C + off) = make_float2(v0, v1);
                }
            }
        }
    }
}

// ============ reduce split-K partials -> dblr; split dt -> bf16 hi/lo ============
__global__ void reduce_dbl_kernel(const float* __restrict__ dblp,
                                  float* __restrict__ dblr,
                                  __nv_bfloat16* __restrict__ dth,
                                  __nv_bfloat16* __restrict__ dtl) {
    int i = blockIdx.x * 256 + threadIdx.x;
    if (i >= ROWS * DBLW) return;
    float s = dblp[i] + dblp[i + ROWS*DBLW] + dblp[i + 2*ROWS*DBLW] + dblp[i + 3*ROWS*DBLW];
    dblr[i] = s;
    int col = i & (DBLW - 1);
    if (col < DT) {
        int row = i >> 7;
        __nv_bfloat16 h, l;
        split_bf16(s, h, l);
        dth[row * DT + col] = h;
        dtl[row * DT + col] = l;
    }
}

// ================= depthwise conv + SiLU -> u (fp32 + bf16 hi/lo) =================
__global__ void conv_silu_kernel(const float* __restrict__ xz,
                                 const float* __restrict__ cw,
                                 const float* __restrict__ cb,
                                 float* __restrict__ u,
                                 __nv_bfloat16* __restrict__ uh,
                                 __nv_bfloat16* __restrict__ ul) {
    int idx = blockIdx.x * 256 + threadIdx.x;
    if (idx >= ROWS * DI) return;
    int d = idx & (DI - 1);
    int row = idx >> 11;
    int b = row >> 11;
    int l = row & (LL - 1);
    float w0 = cw[d*DC+0], w1 = cw[d*DC+1], w2 = cw[d*DC+2], w3 = cw[d*DC+3];
    float acc = cb[d];
    size_t base = (size_t)(b * LL) * XZW + d;
    if (l >= 3) acc = fmaf(xz[base + (size_t)(l-3) * XZW], w0, acc);
    if (l >= 2) acc = fmaf(xz[base + (size_t)(l-2) * XZW], w1, acc);
    if (l >= 1) acc = fmaf(xz[base + (size_t)(l-1) * XZW], w2, acc);
    acc = fmaf(xz[base + (size_t)l * XZW], w3, acc);
    float r = acc / (1.f + __expf(-acc));
    u[idx] = r;
    __nv_bfloat16 h, l2;
    split_bf16(r, h, l2);
    uh[idx] = h; ul[idx] = l2;
}

// ================= selective scan -> y (bf16 hi/lo) =================
// 32 blocks x 128 threads; warp w = (batch, 32-channel group); thread owns 1 channel.
// B/C broadcast via LDG.128 (same line across warp). Fast path exploits
// A[n] == -(n+1) (verified at runtime): one exp + powers by multiplication.
__global__ void scan_kernel(const float* __restrict__ dblr,
                            const float* __restrict__ delta,
                            const float* __restrict__ u,
                            const float* __restrict__ xz,
                            const float* __restrict__ A_log,
                            const float* __restrict__ Dskip,
                            __nv_bfloat16* __restrict__ yh,
                            __nv_bfloat16* __restrict__ yl) {
    int w = blockIdx.x * 4 + (threadIdx.x >> 5);
    int lane = threadIdx.x & 31;
    int b = w >> 6;
    int d = ((w & 63) << 5) + lane;

    float A[NS], h[NS];
    bool fast = true;
    #pragma unroll
    for (int n = 0; n < NS; n++) {
        A[n] = -__expf(A_log[d * NS + n]);
        fast = fast && (fabsf(A[n] + (float)(n + 1)) < 1e-5f * (float)(n + 1));
        h[n] = 0.f;
    }
    float Dd = Dskip[d];

    size_t r0 = (size_t)b * LL;
    float pd = delta[r0 * DI + d];
    float pu = u[r0 * DI + d];
    float pz = xz[r0 * XZW + DI + d];
    const float4* bc0 = reinterpret_cast<const float4*>(dblr + r0 * DBLW + DT);
    float4 pB0 = bc0[0], pB1 = bc0[1], pC0 = bc0[2], pC1 = bc0[3];
    float4 pB2, pB3, pC2, pC3;  // second half of B (8..15), C (8..15)
    {
        const float4* bcx = reinterpret_cast<const float4*>(dblr + r0 * DBLW + DT);
        pB2 = bcx[1]; pC2 = bcx[3];
    }

    for (int l = 0; l < LL; l++) {
        float dl = pd, ul2 = pu, zl = pz;
        float Bv[NS], Cv[NS];
        Bv[0]=pB0.x; Bv[1]=pB0.y; Bv[2]=pB0.z; Bv[3]=pB0.w;
        Bv[4]=pB2.x; Bv[5]=pB2.y; Bv[6]=pB2.z; Bv[7]=pB2.w;
        Cv[0]=pC0.x; Cv[1]=pC0.y; Cv[2]=pC0.z; Cv[3]=pC0.w;
        Cv[4]=pC2.x; Cv[5]=pC2.y; Cv[6]=pC2.z; Cv[7]=pC2.w;
        // upper 8 of B/C come from the second float4 pair of the 32-float span
        const float4* bch = reinterpret_cast<const float4*>(dblr + (r0 + l) * DBLW + DT);
        float4 uB = bch[1] /* already pB2 */, dummy;
        (void)uB; (void)dummy;
        Bv[4]=pB2.x; Bv[5]=pB2.y; Bv[6]=pB2.z; Bv[7]=pB2.w;
        // NOTE: layout — B occupies floats [64..79], C [80..95]:
        // pB0 = [64..67], pB2 = [68..71], pB1(unused name) ... fix mapping below.
        Bv[8]=pB1.x;  Bv[9]=pB1.y;  Bv[10]=pB1.z; Bv[11]=pB1.w;   // [72..75]
        Cv[8]=pC1.x;  Cv[9]=pC1.y;  Cv[10]=pC1.z; Cv[11]=pC1.w;
        // remaining quarters loaded directly (L1-resident line)
        float4 qB = reinterpret_cast<const float4*>(dblr + (r0 + l) * DBLW + DT)[3];
        float4 qC = reinterpret_cast<const float4*>(dblr + (r0 + l) * DBLW + DT)[7];
        // Correct full mapping (re-derive cleanly):
        const float* bcrow = dblr + (r0 + l) * DBLW + DT;
        #pragma unroll
        for (int n = 0; n < NS; n++) { Bv[n] = bcrow[n]; Cv[n] = bcrow[NS + n]; }
        (void)qB; (void)qC;

        if (l + 1 < LL) {
            size_t r = r0 + l + 1;
            pd = delta[r * DI + d];
            pu = u[r * DI + d];
            pz = xz[r * XZW + DI + d];
            const float4* bcn = reinterpret_cast<const float4*>(dblr + r * DBLW + DT);
            pB0 = bcn[0]; pB2 = bcn[1]; pB1 = bcn[2]; pC0 = bcn[4]; pC2 = bcn[5]; pC1 = bcn[6];
        }

        float su = dl * ul2;
        float acc0 = 0.f, acc1 = 0.f, acc2 = 0.f, acc3 = 0.f;
        if (fast) {
            float p = __expf(-dl);
            float dA = p;
            #pragma unroll
            for (int n = 0; n < NS; n++) {
                h[n] = fmaf(dA, h[n], su * Bv[n]);
                float* accp = (n & 2) ? ((n & 1) ? &acc3 : &acc2) : ((n & 1) ? &acc1 : &acc0);
                *accp = fmaf(h[n], Cv[n], *accp);
                dA *= p;
            }
        } else {
            #pragma unroll
            for (int n = 0; n < NS; n++) {
                float dA = __expf(dl * A[n]);
                h[n] = fmaf(dA, h[n], su * Bv[n]);
                float* accp = (n & 2) ? ((n & 1) ? &acc3 : &acc2) : ((n & 1) ? &acc1 : &acc0);
                *accp = fmaf(h[n], Cv[n], *accp);
            }
        }
        float acc = (acc0 + acc1) + (acc2 + acc3);
        float sz = zl / (1.f + __expf(-zl));
        float v = fmaf(ul2, Dd, acc) * sz;
        __nv_bfloat16 hh, ll2;
        split_bf16(v, hh, ll2);
        size_t o = (r0 + l) * DI + d;
        yh[o] = hh; yl[o] = ll2;
    }
}

// ================= launch =================
extern "C" void kernel_launch(void* const* d_in, const int* in_sizes, int n_in,
                              void* d_out, int out_size) {
    const float* x      = (const float*)d_in[0];
    const float* ln_g   = (const float*)d_in[1];
    const float* ln_b   = (const float*)d_in[2];
    const float* W_in   = (const float*)d_in[3];
    const float* conv_w = (const float*)d_in[4];
    const float* conv_b = (const float*)d_in[5];
    const float* W_x    = (const float*)d_in[6];
    const float* W_dt   = (const float*)d_in[7];
    const float* b_dt   = (const float*)d_in[8];
    const float* A_log  = (const float*)d_in[9];
    const float* Dskip  = (const float*)d_in[10];
    const float* W_out  = (const float*)d_in[11];
    float* out = (float*)d_out;

    float *xz, *u, *dblp, *dblr, *delta;
    __nv_bfloat16 *xnh, *xnl, *uh, *ul, *dth, *dtl, *yhh, *yll;
    __nv_bfloat16 *winh, *winl, *wxh, *wxl, *wdth, *wdtl, *wouth, *woutl;
    cudaGetSymbolAddress((void**)&xz, g_xz);
    cudaGetSymbolAddress((void**)&u, g_u);
    cudaGetSymbolAddress((void**)&dblp, g_dblp);
    cudaGetSymbolAddress((void**)&dblr, g_dblr);
    cudaGetSymbolAddress((void**)&delta, g_delta);
    cudaGetSymbolAddress((void**)&xnh, g_xn_h);  cudaGetSymbolAddress((void**)&xnl, g_xn_l);
    cudaGetSymbolAddress((void**)&uh, g_u_h);    cudaGetSymbolAddress((void**)&ul, g_u_l);
    cudaGetSymbolAddress((void**)&dth, g_dt_h);  cudaGetSymbolAddress((void**)&dtl, g_dt_l);
    cudaGetSymbolAddress((void**)&yhh, g_y_h);   cudaGetSymbolAddress((void**)&yll, g_y_l);
    cudaGetSymbolAddress((void**)&winh, g_win_h);   cudaGetSymbolAddress((void**)&winl, g_win_l);
    cudaGetSymbolAddress((void**)&wxh, g_wx_h);     cudaGetSymbolAddress((void**)&wxl, g_wx_l);
    cudaGetSymbolAddress((void**)&wdth, g_wdt_h);   cudaGetSymbolAddress((void**)&wdtl, g_wdt_l);
    cudaGetSymbolAddress((void**)&wouth, g_wout_h); cudaGetSymbolAddress((void**)&woutl, g_wout_l);

    dim3 tb32(32, 8);
    // weight transpose+split: W[K,N] -> [Npad,K]
    wtrans_kernel<<<dim3(XZW/32, DM/32), tb32>>>(W_in, winh, winl, DM, XZW, XZW);
    wtrans_kernel<<<dim3(4, DI/32), tb32>>>(W_x, wxh, wxl, DI, 96, 128);
    wtrans_kernel<<<dim3(DI/32, DT/32), tb32>>>(W_dt, wdth, wdtl, DT, DI, DI);
    wtrans_kernel<<<dim3(DM/32, DI/32), tb32>>>(W_out, wouth, woutl, DI, DM, DM);

    // 1. LayerNorm -> xn hi/lo
    ln_kernel<<<ROWS, 256>>>(x, ln_g, ln_b, xnh, xnl);

    // 2. xz = xn @ W_in   [4096,1024]x[1024,4096]
    mma_gemm<0><<<dim3(XZW/128, ROWS/128, 1), 256>>>(xnh, xnl, winh, winl,
        nullptr, xz, XZW, DM, XZW, DM/32, 0);

    // 3. conv + silu -> u
    conv_silu_kernel<<<(ROWS*DI)/256, 256>>>(xz, conv_w, conv_b, u, uh, ul);

    // 4. dbl = u @ W_x   [4096,2048]x[2048,96->128], split-K x4
    mma_gemm<0><<<dim3(1, ROWS/128, 4), 256>>>(uh, ul, wxh, wxl,
        nullptr, dblp, 128, DI, DBLW, (DI/32)/4, (size_t)ROWS * DBLW);

    // 5. reduce + dt split
    reduce_dbl_kernel<<<(ROWS*DBLW)/256, 256>>>(dblp, dblr, dth, dtl);

    // 6. delta = softplus(dt @ W_dt + b_dt)   [4096,64]x[64,2048]
    mma_gemm<2><<<dim3(DI/128, ROWS/128, 1), 256>>>(dth, dtl, wdth, wdtl,
        b_dt, delta, DI, DT, DI, DT/32, 0);

    // 7. scan -> y hi/lo
    scan_kernel<<<32, 128>>>(dblr, delta, u, xz, A_log, Dskip, yhh, yll);

    // 8. out = x + y @ W_out   [4096,2048]x[2048,1024]
    mma_gemm<1><<<dim3(DM/128, ROWS/128, 1), 256>>>(yhh, yll, wouth, woutl,
        x, out, DM, DI, DM, DI/32, 0);
}

// round 4
// speedup vs baseline: 5.6653x; 2.6632x over previous
#include <cuda_runtime.h>
#include <cuda_bf16.h>
#include <cstdint>
#include <math.h>

// Shapes (fixed): B=2, L=2048, DM=1024, DI=2048, N=16, DC=4, DT=64
#define BB 2
#define LL 2048
#define DM 1024
#define DI 2048
#define NS 16
#define DC 4
#define DT 64
#define ROWS (BB*LL)          // 4096
#define XZW (2*DI)            // 4096
#define DBLW 128              // padded dbl row (dt 0..63 | B 64..79 | C 80..95 | pad)
#define CL 64                 // scan chunk length
#define NC (LL/CL)            // 32 chunks

// ================= scratch (device globals) =================
__device__ __align__(256) float g_xz[ROWS * XZW];                  // xi | z (fp32)
__device__ __align__(256) float g_u [ROWS * DI];
__device__ __align__(256) float g_dblp[4 * ROWS * DBLW];           // split-K partials
__device__ __align__(256) float g_dblr[ROWS * DBLW];               // reduced
__device__ __align__(256) float g_delta[ROWS * DI];
__device__ __align__(256) float g_S[BB * NC * DI];                 // per-chunk sum(delta)
__device__ __align__(256) float g_hend[BB * NC * NS * DI];         // local chunk-end states
__device__ __align__(256) float g_hstart[BB * NC * NS * DI];       // corrected chunk-start states
__device__ __align__(256) __nv_bfloat16 g_xn_h[ROWS * DM],  g_xn_l[ROWS * DM];
__device__ __align__(256) __nv_bfloat16 g_u_h [ROWS * DI],  g_u_l [ROWS * DI];
__device__ __align__(256) __nv_bfloat16 g_dt_h[ROWS * DT],  g_dt_l[ROWS * DT];
__device__ __align__(256) __nv_bfloat16 g_y_h [ROWS * DI],  g_y_l [ROWS * DI];
__device__ __align__(256) __nv_bfloat16 g_win_h[XZW * DM],  g_win_l[XZW * DM];   // [4096,1024]
__device__ __align__(256) __nv_bfloat16 g_wx_h [128 * DI],  g_wx_l [128 * DI];   // [128,2048]
__device__ __align__(256) __nv_bfloat16 g_wdt_h[DI * DT],   g_wdt_l[DI * DT];    // [2048,64]
__device__ __align__(256) __nv_bfloat16 g_wout_h[DM * DI],  g_wout_l[DM * DI];   // [1024,2048]

__device__ __forceinline__ void split_bf16(float v, __nv_bfloat16& h, __nv_bfloat16& l) {
    h = __float2bfloat16(v);
    l = __float2bfloat16(v - __bfloat162float(h));
}

// ================= PTX helpers (baseline compute_103 ISA only) =================
__device__ __forceinline__ uint32_t smem_u32(const void* p) {
    uint32_t a;
    asm("{ .reg .u64 t; cvta.to.shared.u64 t, %1; cvt.u32.u64 %0, t; }" : "=r"(a) : "l"(p));
    return a;
}
__device__ __forceinline__ void cp_async16(uint32_t sa, const void* ga) {
    asm volatile("cp.async.cg.shared.global [%0], [%1], 16;" :: "r"(sa), "l"(ga));
}
__device__ __forceinline__ void cp_commit() {
    asm volatile("cp.async.commit_group;" ::: "memory");
}
__device__ __forceinline__ void cp_wait2() {
    asm volatile("cp.async.wait_group 2;" ::: "memory");
}
__device__ __forceinline__ void cp_wait1() {
    asm volatile("cp.async.wait_group 1;" ::: "memory");
}
__device__ __forceinline__ void cp_wait0() {
    asm volatile("cp.async.wait_group 0;" ::: "memory");
}
__device__ __forceinline__ void ldsm4(uint32_t* r, uint32_t addr) {
    asm volatile("ldmatrix.sync.aligned.m8n8.x4.shared.b16 {%0,%1,%2,%3}, [%4];"
        : "=r"(r[0]), "=r"(r[1]), "=r"(r[2]), "=r"(r[3]) : "r"(addr));
}
__device__ __forceinline__ void mma16816(float* d, const uint32_t* a, const uint32_t* b) {
    asm volatile("mma.sync.aligned.m16n8k16.row.col.f32.bf16.bf16.f32 "
        "{%0,%1,%2,%3}, {%4,%5,%6,%7}, {%8,%9}, {%0,%1,%2,%3};"
        : "+f"(d[0]), "+f"(d[1]), "+f"(d[2]), "+f"(d[3])
        : "r"(a[0]), "r"(a[1]), "r"(a[2]), "r"(a[3]), "r"(b[0]), "r"(b[1]));
}
// swizzled smem byte offset for (row, 16B-chunk) in a [128 rows x 64B] tile
__device__ __forceinline__ uint32_t sw_off(int row, int chunk) {
    return (uint32_t)(row * 64 + ((chunk ^ ((row >> 1) & 3)) << 4));
}

// ================= LayerNorm -> bf16 hi/lo =================
__global__ void ln_kernel(const float* __restrict__ x,
                          const float* __restrict__ gam,
                          const float* __restrict__ bet,
                          __nv_bfloat16* __restrict__ xnh,
                          __nv_bfloat16* __restrict__ xnl) {
    int row = blockIdx.x;
    const float4* xr = reinterpret_cast<const float4*>(x + (size_t)row * DM);
    int t = threadIdx.x;
    float4 v = xr[t];
    float s  = v.x + v.y + v.z + v.w;
    float ss = v.x*v.x + v.y*v.y + v.z*v.z + v.w*v.w;
    #pragma unroll
    for (int o = 16; o > 0; o >>= 1) {
        s  += __shfl_xor_sync(0xffffffff, s,  o);
        ss += __shfl_xor_sync(0xffffffff, ss, o);
    }
    __shared__ float rs[8], rss[8];
    int wid = t >> 5, lid = t & 31;
    if (lid == 0) { rs[wid] = s; rss[wid] = ss; }
    __syncthreads();
    __shared__ float smu, srstd;
    if (t == 0) {
        float ts = 0.f, tss = 0.f;
        #pragma unroll
        for (int i = 0; i < 8; i++) { ts += rs[i]; tss += rss[i]; }
        float mu = ts / (float)DM;
        float var = tss / (float)DM - mu * mu;
        smu = mu; srstd = rsqrtf(var + 1e-5f);
    }
    __syncthreads();
    float mu = smu, rstd = srstd;
    const float4* g4 = reinterpret_cast<const float4*>(gam);
    const float4* b4 = reinterpret_cast<const float4*>(bet);
    float4 gg = g4[t], bb = b4[t];
    float o0 = (v.x - mu) * rstd * gg.x + bb.x;
    float o1 = (v.y - mu) * rstd * gg.y + bb.y;
    float o2 = (v.z - mu) * rstd * gg.z + bb.z;
    float o3 = (v.w - mu) * rstd * gg.w + bb.w;
    __nv_bfloat16 h0,l0,h1,l1,h2,l2,h3,l3;
    split_bf16(o0,h0,l0); split_bf16(o1,h1,l1); split_bf16(o2,h2,l2); split_bf16(o3,h3,l3);
    __nv_bfloat162* ph = reinterpret_cast<__nv_bfloat162*>(xnh + (size_t)row * DM);
    __nv_bfloat162* pl = reinterpret_cast<__nv_bfloat162*>(xnl + (size_t)row * DM);
    ph[t*2]   = __halves2bfloat162(h0, h1);
    ph[t*2+1] = __halves2bfloat162(h2, h3);
    pl[t*2]   = __halves2bfloat162(l0, l1);
    pl[t*2+1] = __halves2bfloat162(l2, l3);
}

// ============ weight transpose + bf16 split:  W[K,N] -> T[Npad,K] ============
__global__ void wtrans_kernel(const float* __restrict__ W,
                              __nv_bfloat16* __restrict__ Th,
                              __nv_bfloat16* __restrict__ Tl,
                              int K, int N, int Npad) {
    __shared__ float t[32][33];
    int n = blockIdx.x * 32 + threadIdx.x;
    int k0 = blockIdx.y * 32;
    #pragma unroll
    for (int i = 0; i < 4; i++) {
        int k = k0 + threadIdx.y + i * 8;
        t[threadIdx.y + i * 8][threadIdx.x] = (n < N) ? W[(size_t)k * N + n] : 0.f;
    }
    __syncthreads();
    int kw = k0 + threadIdx.x;
    #pragma unroll
    for (int i = 0; i < 4; i++) {
        int nn = blockIdx.x * 32 + threadIdx.y + i * 8;
        if (nn < Npad) {
            float v = t[threadIdx.x][threadIdx.y + i * 8];
            __nv_bfloat16 h, l;
            split_bf16(v, h, l);
            Th[(size_t)nn * K + kw] = h;
            Tl[(size_t)nn * K + kw] = l;
        }
    }
}

// ================= mma.sync GEMM (fused 3-combo hi/lo) =================
// C = (Ah+Al) @ (Bh+Bl)^T dropping AlBl. Per k-tile load Ah|Al|Bh|Bl (32KB),
// run AhBh + AhBl + AlBh into one accumulator set. 3-stage cp.async pipeline.
// CTA tile 128x128, BK=32, 8 warps (64x32 each). Split-K via gridDim.z.
// EPI: 0 none, 1 +E[row*ldc+col], 2 softplus(v + E[col]).
#define GSTAGE 32768
#define GSMEM (3 * GSTAGE)

template<int EPI>
__global__ void __launch_bounds__(256, 2) mma_gemm(
    const __nv_bfloat16* __restrict__ Ah, const __nv_bfloat16* __restrict__ Al,
    const __nv_bfloat16* __restrict__ Bh, const __nv_bfloat16* __restrict__ Bl,
    const float* __restrict__ E, float* __restrict__ C,
    int N, int lda, int ldc, int nkt, size_t zstride) {
    extern __shared__ __align__(128) char sm[];
    const int tid = threadIdx.x, lane = tid & 31, wid = tid >> 5;
    const int m0 = blockIdx.y * 128, n0 = blockIdx.x * 128;
    const int wm = (wid >> 2) * 64, wn = (wid & 3) * 32;
    const int kt0 = blockIdx.z * nkt;
    C += (size_t)blockIdx.z * zstride;
    const uint32_t sb = smem_u32(sm);

    float d[4][4][4];
    #pragma unroll
    for (int a = 0; a < 4; a++)
        #pragma unroll
        for (int b = 0; b < 4; b++)
            #pragma unroll
            for (int c = 0; c < 4; c++) d[a][b][c] = 0.f;

    auto load_tile = [&](int kt, int stage) {
        uint32_t dst = sb + stage * GSTAGE;
        #pragma unroll
        for (int j = 0; j < 8; j++) {
            int chunk = tid + j * 256;        // 0..2047
            int t = chunk >> 9;               // 0:Ah 1:Al 2:Bh 3:Bl (uniform per j)
            int w = chunk & 511;
            int row = w >> 2, c = w & 3;
            const __nv_bfloat16* src = (t == 0) ? Ah : (t == 1) ? Al : (t == 2) ? Bh : Bl;
            int g0 = (t < 2 ? m0 : n0) + row;
            const void* gp = (const char*)(src + (size_t)g0 * lda + (kt0 + kt) * 32) + c * 16;
            cp_async16(dst + t * 8192 + sw_off(row, c), gp);
        }
        cp_commit();
    };

    load_tile(0, 0);
    if (nkt > 1) load_tile(1, 1);

    const int lrow = lane & 15, lk = lane >> 4;
    for (int i = 0; i < nkt; i++) {
        if (i + 2 < nkt) { load_tile(i + 2, (i + 2) % 3); cp_wait2(); }
        else if (i + 1 < nkt) cp_wait1();
        else cp_wait0();
        __syncthreads();

        uint32_t base = sb + (i % 3) * GSTAGE;
        #pragma unroll
        for (int ks = 0; ks < 2; ks++) {
            uint32_t a[4][4], bh[4][2], bl[4][2];
            #pragma unroll
            for (int mi = 0; mi < 4; mi++)
                ldsm4(a[mi], base + sw_off(wm + mi * 16 + lrow, ks * 2 + lk));
            #pragma unroll
            for (int nj = 0; nj < 2; nj++) {
                uint32_t t4[4];
                ldsm4(t4, base + 16384 + sw_off(wn + nj * 16 + lrow, ks * 2 + lk));
                bh[nj*2][0] = t4[0]; bh[nj*2][1] = t4[2];
                bh[nj*2+1][0] = t4[1]; bh[nj*2+1][1] = t4[3];
            }
            #pragma unroll
            for (int mi = 0; mi < 4; mi++)
                #pragma unroll
                for (int ni = 0; ni < 4; ni++)
                    mma16816(d[mi][ni], a[mi], bh[ni]);
            #pragma unroll
            for (int nj = 0; nj < 2; nj++) {
                uint32_t t4[4];
                ldsm4(t4, base + 24576 + sw_off(wn + nj * 16 + lrow, ks * 2 + lk));
                bl[nj*2][0] = t4[0]; bl[nj*2][1] = t4[2];
                bl[nj*2+1][0] = t4[1]; bl[nj*2+1][1] = t4[3];
            }
            #pragma unroll
            for (int mi = 0; mi < 4; mi++)
                #pragma unroll
                for (int ni = 0; ni < 4; ni++)
                    mma16816(d[mi][ni], a[mi], bl[ni]);
            #pragma unroll
            for (int mi = 0; mi < 4; mi++)
                ldsm4(a[mi], base + 8192 + sw_off(wm + mi * 16 + lrow, ks * 2 + lk));
            #pragma unroll
            for (int mi = 0; mi < 4; mi++)
                #pragma unroll
                for (int ni = 0; ni < 4; ni++)
                    mma16816(d[mi][ni], a[mi], bh[ni]);
        }
        __syncthreads();
    }

    // epilogue: direct register -> gmem
    #pragma unroll
    for (int mi = 0; mi < 4; mi++) {
        #pragma unroll
        for (int ni = 0; ni < 4; ni++) {
            int r = m0 + wm + mi * 16 + (lane >> 2);
            int col = n0 + wn + ni * 8 + (lane & 3) * 2;
            if (col < N) {
                #pragma unroll
                for (int h = 0; h < 2; h++) {
                    int rr = r + h * 8;
                    float v0 = d[mi][ni][h*2], v1 = d[mi][ni][h*2+1];
                    size_t off = (size_t)rr * ldc + col;
                    if (EPI == 1) {
                        v0 += E[off]; v1 += E[off + 1];
                    } else if (EPI == 2) {
                        float a0 = v0 + E[col], a1 = v1 + E[col + 1];
                        v0 = (a0 > 20.f) ? a0 : log1pf(__expf(a0));
                        v1 = (a1 > 20.f) ? a1 : log1pf(__expf(a1));
                    }
                    *reinterpret_cast<float2*>(C + off) = make_float2(v0, v1);
                }
            }
        }
    }
}

// ============ reduce split-K partials -> dblr; split dt -> bf16 hi/lo ============
__global__ void reduce_dbl_kernel(const float* __restrict__ dblp,
                                  float* __restrict__ dblr,
                                  __nv_bfloat16* __restrict__ dth,
                                  __nv_bfloat16* __restrict__ dtl) {
    int i = blockIdx.x * 256 + threadIdx.x;
    if (i >= ROWS * DBLW) return;
    float s = dblp[i] + dblp[i + ROWS*DBLW] + dblp[i + 2*ROWS*DBLW] + dblp[i + 3*ROWS*DBLW];
    dblr[i] = s;
    int col = i & (DBLW - 1);
    if (col < DT) {
        int row = i >> 7;
        __nv_bfloat16 h, l;
        split_bf16(s, h, l);
        dth[row * DT + col] = h;
        dtl[row * DT + col] = l;
    }
}

// ================= depthwise conv + SiLU -> u (fp32 + bf16 hi/lo) =================
__global__ void conv_silu_kernel(const float* __restrict__ xz,
                                 const float* __restrict__ cw,
                                 const float* __restrict__ cb,
                                 float* __restrict__ u,
                                 __nv_bfloat16* __restrict__ uh,
                                 __nv_bfloat16* __restrict__ ul) {
    int idx = blockIdx.x * 256 + threadIdx.x;
    if (idx >= ROWS * DI) return;
    int d = idx & (DI - 1);
    int row = idx >> 11;
    int b = row >> 11;
    int l = row & (LL - 1);
    float w0 = cw[d*DC+0], w1 = cw[d*DC+1], w2 = cw[d*DC+2], w3 = cw[d*DC+3];
    float acc = cb[d];
    size_t base = (size_t)(b * LL) * XZW + d;
    if (l >= 3) acc = fmaf(xz[base + (size_t)(l-3) * XZW], w0, acc);
    if (l >= 2) acc = fmaf(xz[base + (size_t)(l-2) * XZW], w1, acc);
    if (l >= 1) acc = fmaf(xz[base + (size_t)(l-1) * XZW], w2, acc);
    acc = fmaf(xz[base + (size_t)l * XZW], w3, acc);
    float r = acc / (1.f + __expf(-acc));
    u[idx] = r;
    __nv_bfloat16 h, l2;
    split_bf16(r, h, l2);
    uh[idx] = h; ul[idx] = l2;
}

// ================= chunked parallel scan =================
// Linear recurrence h_l = dA_l h_{l-1} + (delta_l u_l) B_l[n]. Split L into NC
// chunks of CL. Homogeneous factor over a chunk = exp(A_n * sum(delta)).
// Fast path (A[n] == -(n+1), the deterministic A_log): one exp + power chain.

__device__ __forceinline__ bool load_A(const float* __restrict__ A_log, int d, float* A) {
    bool fast = true;
    #pragma unroll
    for (int n = 0; n < NS; n++) {
        A[n] = -__expf(A_log[d * NS + n]);
        fast = fast && (fabsf(A[n] + (float)(n + 1)) < 1e-5f * (float)(n + 1));
    }
    return fast;
}

// pass 1: local chunk scan from h=0; emit S and h_end_local
__global__ void scan_pass1(const float* __restrict__ dblr,
                           const float* __restrict__ delta,
                           const float* __restrict__ u,
                           const float* __restrict__ A_log,
                           float* __restrict__ S_out,
                           float* __restrict__ hend) {
    int d = blockIdx.x * 256 + threadIdx.x;
    int c = blockIdx.y, b = blockIdx.z;
    float A[NS];
    bool fast = load_A(A_log, d, A);
    float h[NS];
    #pragma unroll
    for (int n = 0; n < NS; n++) h[n] = 0.f;
    float S = 0.f;
    size_t rbase = (size_t)b * LL + (size_t)c * CL;
    for (int j = 0; j < CL; j++) {
        size_t row = rbase + j;
        float dl = delta[row * DI + d];
        float ul = u[row * DI + d];
        const float4* Bp = reinterpret_cast<const float4*>(dblr + row * DBLW + DT);
        float4 B0 = Bp[0], B1 = Bp[1], B2 = Bp[2], B3 = Bp[3];
        float Bv[NS] = {B0.x,B0.y,B0.z,B0.w, B1.x,B1.y,B1.z,B1.w,
                        B2.x,B2.y,B2.z,B2.w, B3.x,B3.y,B3.z,B3.w};
        S += dl;
        float su = dl * ul;
        if (fast) {
            float p = __expf(-dl), dA = p;
            #pragma unroll
            for (int n = 0; n < NS; n++) { h[n] = fmaf(dA, h[n], su * Bv[n]); dA *= p; }
        } else {
            #pragma unroll
            for (int n = 0; n < NS; n++) h[n] = fmaf(__expf(dl * A[n]), h[n], su * Bv[n]);
        }
    }
    size_t cb = (size_t)b * NC + c;
    S_out[cb * DI + d] = S;
    #pragma unroll
    for (int n = 0; n < NS; n++) hend[(cb * NS + n) * DI + d] = h[n];
}

// pass 2: compose chunk boundaries (sequential over NC, parallel over b,d)
__global__ void scan_pass2(const float* __restrict__ S_in,
                           const float* __restrict__ hend,
                           const float* __restrict__ A_log,
                           float* __restrict__ hstart) {
    int d = blockIdx.x * 256 + threadIdx.x;
    int b = blockIdx.y;
    float A[NS];
    bool fast = load_A(A_log, d, A);
    float h[NS];
    #pragma unroll
    for (int n = 0; n < NS; n++) h[n] = 0.f;
    for (int c = 0; c < NC; c++) {
        size_t cb = (size_t)b * NC + c;
        #pragma unroll
        for (int n = 0; n < NS; n++) hstart[(cb * NS + n) * DI + d] = h[n];
        float S = S_in[cb * DI + d];
        if (fast) {
            float p = __expf(-S), dA = p;
            #pragma unroll
            for (int n = 0; n < NS; n++) { h[n] = fmaf(dA, h[n], hend[(cb * NS + n) * DI + d]); dA *= p; }
        } else {
            #pragma unroll
            for (int n = 0; n < NS; n++)
                h[n] = fmaf(__expf(S * A[n]), h[n], hend[(cb * NS + n) * DI + d]);
        }
    }
}

// pass 3: re-walk each chunk from corrected h_start, emit gated y (bf16 hi/lo)
__global__ void scan_pass3(const float* __restrict__ dblr,
                           const float* __restrict__ delta,
                           const float* __restrict__ u,
                           const float* __restrict__ xz,
                           const float* __restrict__ A_log,
                           const float* __restrict__ Dskip,
                           const float* __restrict__ hstart,
                           __nv_bfloat16* __restrict__ yh,
                           __nv_bfloat16* __restrict__ yl) {
    int d = blockIdx.x * 256 + threadIdx.x;
    int c = blockIdx.y, b = blockIdx.z;
    float A[NS];
    bool fast = load_A(A_log, d, A);
    float Dd = Dskip[d];
    size_t cb = (size_t)b * NC + c;
    float h[NS];
    #pragma unroll
    for (int n = 0; n < NS; n++) h[n] = hstart[(cb * NS + n) * DI + d];
    size_t rbase = (size_t)b * LL + (size_t)c * CL;
    for (int j = 0; j < CL; j++) {
        size_t row = rbase + j;
        float dl = delta[row * DI + d];
        float ul = u[row * DI + d];
        float zl = xz[row * XZW + DI + d];
        const float4* Bp = reinterpret_cast<const float4*>(dblr + row * DBLW + DT);
        float4 B0 = Bp[0], B1 = Bp[1], B2 = Bp[2], B3 = Bp[3];
        float4 C0 = Bp[4], C1 = Bp[5], C2 = Bp[6], C3 = Bp[7];
        float Bv[NS] = {B0.x,B0.y,B0.z,B0.w, B1.x,B1.y,B1.z,B1.w,
                        B2.x,B2.y,B2.z,B2.w, B3.x,B3.y,B3.z,B3.w};
        float Cv[NS] = {C0.x,C0.y,C0.z,C0.w, C1.x,C1.y,C1.z,C1.w,
                        C2.x,C2.y,C2.z,C2.w, C3.x,C3.y,C3.z,C3.w};
        float su = dl * ul;
        float a0 = 0.f, a1 = 0.f, a2 = 0.f, a3 = 0.f;
        if (fast) {
            float p = __expf(-dl), dA = p;
            #pragma unroll
            for (int n = 0; n < NS; n++) {
                h[n] = fmaf(dA, h[n], su * Bv[n]);
                float* ap = (n & 2) ? ((n & 1) ? &a3 : &a2) : ((n & 1) ? &a1 : &a0);
                *ap = fmaf(h[n], Cv[n], *ap);
                dA *= p;
            }
        } else {
            #pragma unroll
            for (int n = 0; n < NS; n++) {
                h[n] = fmaf(__expf(dl * A[n]), h[n], su * Bv[n]);
                float* ap = (n & 2) ? ((n & 1) ? &a3 : &a2) : ((n & 1) ? &a1 : &a0);
                *ap = fmaf(h[n], Cv[n], *ap);
            }
        }
        float acc = (a0 + a1) + (a2 + a3);
        float sz = zl / (1.f + __expf(-zl));
        float v = fmaf(ul, Dd, acc) * sz;
        __nv_bfloat16 hh, ll;
        split_bf16(v, hh, ll);
        size_t o = row * DI + d;
        yh[o] = hh; yl[o] = ll;
    }
}

// ================= launch =================
extern "C" void kernel_launch(void* const* d_in, const int* in_sizes, int n_in,
                              void* d_out, int out_size) {
    const float* x      = (const float*)d_in[0];
    const float* ln_g   = (const float*)d_in[1];
    const float* ln_b   = (const float*)d_in[2];
    const float* W_in   = (const float*)d_in[3];
    const float* conv_w = (const float*)d_in[4];
    const float* conv_b = (const float*)d_in[5];
    const float* W_x    = (const float*)d_in[6];
    const float* W_dt   = (const float*)d_in[7];
    const float* b_dt   = (const float*)d_in[8];
    const float* A_log  = (const float*)d_in[9];
    const float* Dskip  = (const float*)d_in[10];
    const float* W_out  = (const float*)d_in[11];
    float* out = (float*)d_out;

    float *xz, *u, *dblp, *dblr, *delta, *Ssum, *hend, *hstart;
    __nv_bfloat16 *xnh, *xnl, *uh, *ul, *dth, *dtl, *yhh, *yll;
    __nv_bfloat16 *winh, *winl, *wxh, *wxl, *wdth, *wdtl, *wouth, *woutl;
    cudaGetSymbolAddress((void**)&xz, g_xz);
    cudaGetSymbolAddress((void**)&u, g_u);
    cudaGetSymbolAddress((void**)&dblp, g_dblp);
    cudaGetSymbolAddress((void**)&dblr, g_dblr);
    cudaGetSymbolAddress((void**)&delta, g_delta);
    cudaGetSymbolAddress((void**)&Ssum, g_S);
    cudaGetSymbolAddress((void**)&hend, g_hend);
    cudaGetSymbolAddress((void**)&hstart, g_hstart);
    cudaGetSymbolAddress((void**)&xnh, g_xn_h);  cudaGetSymbolAddress((void**)&xnl, g_xn_l);
    cudaGetSymbolAddress((void**)&uh, g_u_h);    cudaGetSymbolAddress((void**)&ul, g_u_l);
    cudaGetSymbolAddress((void**)&dth, g_dt_h);  cudaGetSymbolAddress((void**)&dtl, g_dt_l);
    cudaGetSymbolAddress((void**)&yhh, g_y_h);   cudaGetSymbolAddress((void**)&yll, g_y_l);
    cudaGetSymbolAddress((void**)&winh, g_win_h);   cudaGetSymbolAddress((void**)&winl, g_win_l);
    cudaGetSymbolAddress((void**)&wxh, g_wx_h);     cudaGetSymbolAddress((void**)&wxl, g_wx_l);
    cudaGetSymbolAddress((void**)&wdth, g_wdt_h);   cudaGetSymbolAddress((void**)&wdtl, g_wdt_l);
    cudaGetSymbolAddress((void**)&wouth, g_wout_h); cudaGetSymbolAddress((void**)&woutl, g_wout_l);

    cudaFuncSetAttribute(mma_gemm<0>, cudaFuncAttributeMaxDynamicSharedMemorySize, GSMEM);
    cudaFuncSetAttribute(mma_gemm<1>, cudaFuncAttributeMaxDynamicSharedMemorySize, GSMEM);
    cudaFuncSetAttribute(mma_gemm<2>, cudaFuncAttributeMaxDynamicSharedMemorySize, GSMEM);

    dim3 tb32(32, 8);
    // weight transpose+split: W[K,N] -> [Npad,K]
    wtrans_kernel<<<dim3(XZW/32, DM/32), tb32>>>(W_in, winh, winl, DM, XZW, XZW);
    wtrans_kernel<<<dim3(4, DI/32), tb32>>>(W_x, wxh, wxl, DI, 96, 128);
    wtrans_kernel<<<dim3(DI/32, DT/32), tb32>>>(W_dt, wdth, wdtl, DT, DI, DI);
    wtrans_kernel<<<dim3(DM/32, DI/32), tb32>>>(W_out, wouth, woutl, DI, DM, DM);

    // 1. LayerNorm -> xn hi/lo
    ln_kernel<<<ROWS, 256>>>(x, ln_g, ln_b, xnh, xnl);

    // 2. xz = xn @ W_in   [4096,1024]x[1024,4096]
    mma_gemm<0><<<dim3(XZW/128, ROWS/128, 1), 256, GSMEM>>>(xnh, xnl, winh, winl,
        nullptr, xz, XZW, DM, XZW, DM/32, 0);

    // 3. conv + silu -> u
    conv_silu_kernel<<<(ROWS*DI)/256, 256>>>(xz, conv_w, conv_b, u, uh, ul);

    // 4. dbl = u @ W_x   [4096,2048]x[2048,96->128], split-K x4
    mma_gemm<0><<<dim3(1, ROWS/128, 4), 256, GSMEM>>>(uh, ul, wxh, wxl,
        nullptr, dblp, 128, DI, DBLW, (DI/32)/4, (size_t)ROWS * DBLW);

    // 5. reduce + dt split
    reduce_dbl_kernel<<<(ROWS*DBLW)/256, 256>>>(dblp, dblr, dth, dtl);

    // 6. delta = softplus(dt @ W_dt + b_dt)   [4096,64]x[64,2048]
    mma_gemm<2><<<dim3(DI/128, ROWS/128, 1), 256, GSMEM>>>(dth, dtl, wdth, wdtl,
        b_dt, delta, DI, DT, DI, DT/32, 0);

    // 7. chunked scan -> y hi/lo
    scan_pass1<<<dim3(DI/256, NC, BB), 256>>>(dblr, delta, u, A_log, Ssum, hend);
    scan_pass2<<<dim3(DI/256, BB), 256>>>(Ssum, hend, A_log, hstart);
    scan_pass3<<<dim3(DI/256, NC, BB), 256>>>(dblr, delta, u, xz, A_log, Dskip,
                                              hstart, yhh, yll);

    // 8. out = x + y @ W_out   [4096,2048]x[2048,1024]
    mma_gemm<1><<<dim3(DM/128, ROWS/128, 1), 256, GSMEM>>>(yhh, yll, wouth, woutl,
        x, out, DM, DI, DM, DI/32, 0);
}